// round 6
// baseline (speedup 1.0000x reference)
#include <cuda_runtime.h>
#include <cuda_bf16.h>
#include <stdint.h>

// Problem constants: N=100000 nodes, E=600000 edges, D=128.
#define N_MAX 100000
#define E_MAX 600000
#define DIM   128

// multi-block scan geometry
#define SC_BLK   256
#define SC_PER   8
#define SC_CHUNK (SC_BLK * SC_PER)            // 2048
#define SC_NBLK  ((N_MAX + SC_CHUNK - 1) / SC_CHUNK)   // 49 (must be <= 64)

// ---- device scratch (no cudaMalloc allowed) ----
__device__ int   g_deg[N_MAX];
__device__ int   g_off[N_MAX + 1];
__device__ int   g_cur[N_MAX];
__device__ int   g_csr[E_MAX];
__device__ int   g_part[64];
__device__ __align__(16) float g_WT[256 * DIM];   // [Wl ; Wr]^T tf32

__device__ __forceinline__ float to_tf32(float x) {
    float y;
    asm("cvt.rna.tf32.f32 %0, %1;" : "=f"(y) : "f"(x));
    return y;
}

// ---------------------------------------------------------------------------
// 0) merged init: zero degree counters + transpose/round weights
__global__ void init_kernel(const float* __restrict__ Wl,
                            const float* __restrict__ Wr, int n) {
    int i = blockIdx.x * blockDim.x + threadIdx.x;
    if (i < n) g_deg[i] = 0;
    if (i < 256 * DIM) {
        int k = i >> 7;
        int j = i & 127;
        float v = (k < DIM) ? Wl[j * DIM + k] : Wr[j * DIM + (k - DIM)];
        g_WT[i] = to_tf32(v);
    }
}

// 1) histogram of destination nodes (edge_index is int32)
__global__ void hist_kernel(const int* __restrict__ ei, int E) {
    int i = blockIdx.x * blockDim.x + threadIdx.x;
    if (i < E) {
        int dst = ei[E + i];
        if (dst >= 0 && dst < N_MAX) atomicAdd(&g_deg[dst], 1);
    }
}

// 2) per-chunk partial sums
__global__ void part_sum_kernel(int n) {
    __shared__ int s[SC_BLK];
    int t = threadIdx.x;
    int base = blockIdx.x * SC_CHUNK + t * SC_PER;
    int sum = 0;
#pragma unroll
    for (int j = 0; j < SC_PER; ++j) {
        int i = base + j;
        if (i < n) sum += g_deg[i];
    }
    s[t] = sum;
    __syncthreads();
#pragma unroll
    for (int off = SC_BLK / 2; off > 0; off >>= 1) {
        if (t < off) s[t] += s[t + off];
        __syncthreads();
    }
    if (t == 0) g_part[blockIdx.x] = s[0];
}

// 3) offsets: each block scans the chunk partials itself, then its own chunk.
__global__ void off_kernel(int n, int E, int nblk) {
    __shared__ int sp[64];
    __shared__ int s[SC_BLK];
    int t = threadIdx.x;

    if (t < 64) sp[t] = (t < nblk) ? g_part[t] : 0;
    __syncthreads();
#pragma unroll
    for (int off = 1; off < 64; off <<= 1) {
        int tmp = (t < 64 && t >= off) ? sp[t - off] : 0;
        __syncthreads();
        if (t < 64) sp[t] += tmp;
        __syncthreads();
    }
    // sp[] = INCLUSIVE prefix of chunk partials.

    int base = blockIdx.x * SC_CHUNK + t * SC_PER;
    int v[SC_PER];
    int sum = 0;
#pragma unroll
    for (int j = 0; j < SC_PER; ++j) {
        int i = base + j;
        v[j] = (i < n) ? g_deg[i] : 0;
        sum += v[j];
    }
    s[t] = sum;
    __syncthreads();
#pragma unroll
    for (int off = 1; off < SC_BLK; off <<= 1) {
        int tmp = (t >= off) ? s[t - off] : 0;
        __syncthreads();
        s[t] += tmp;
        __syncthreads();
    }
    int block_total = s[SC_BLK - 1];
    int chunk_prefix = sp[blockIdx.x] - block_total;
    int run = chunk_prefix + s[t] - sum;
#pragma unroll
    for (int j = 0; j < SC_PER; ++j) {
        int i = base + j;
        if (i < n) {
            g_off[i] = run;
            g_cur[i] = run;
            run += v[j];
        }
    }
    if (blockIdx.x == 0 && t == 0) g_off[n] = E;
}

// 4) scatter src ids into CSR slots
__global__ void scatter_kernel(const int* __restrict__ ei, int E) {
    int i = blockIdx.x * blockDim.x + threadIdx.x;
    if (i < E) {
        int src = ei[i];
        int dst = ei[E + i];
        if (dst >= 0 && dst < N_MAX) {
            int pos = atomicAdd(&g_cur[dst], 1);
            if (pos >= 0 && pos < E_MAX) g_csr[pos] = src;
        }
    }
}

// ---------------------------------------------------------------------------
// FUSED aggregation + tf32 tensor-core GEMM.
// Phase 1: 8 warps aggregate the block's 128 nodes into agg_s (tf32-rounded).
// Phase 2: out[128,128] = [agg_s | feat](x256) x g_WT + b_l, with feat chunks
//          streamed in place over already-consumed agg_s columns.
#define GBM 128
#define GKB 32
#define AGG_STRIDE 132   // 132 % 32 == 4 -> frag reads (4g+t) conflict-free
#define BS_STRIDE  136   // frag reads (8t+g) conflict-free
#define AGG_FLOATS (GBM * AGG_STRIDE)       // 16896
#define BS_FLOATS  (GKB * BS_STRIDE)        // 4352
#define SMEM_BYTES ((AGG_FLOATS + BS_FLOATS) * 4)   // 84992 B

__global__ __launch_bounds__(256, 2)
void fused_kernel(const float* __restrict__ feat,
                  const float* __restrict__ b_l,
                  float* __restrict__ out, int n) {
    extern __shared__ float smem[];
    float* agg_s = smem;                 // [128][AGG_STRIDE]
    float* Bs = smem + AGG_FLOATS;       // [32][BS_STRIDE]

    int tid = threadIdx.x;
    int wid = tid >> 5;
    int lane = tid & 31;
    int g = lane >> 2, t = lane & 3;
    int block_row = blockIdx.x * GBM;

    // ---------------- Phase 1: aggregate 128 nodes ----------------
#pragma unroll 1
    for (int i = 0; i < 16; ++i) {
        int lrow = wid * 16 + i;
        int grow = block_row + lrow;
        float4 a4 = make_float4(0.f, 0.f, 0.f, 0.f);
        if (grow < n) {
            int beg = g_off[grow];
            int end = g_off[grow + 1];
            int s_next = (beg < end) ? g_csr[beg] : 0;
            for (int e = beg; e < end; ++e) {
                int s = s_next;
                if (e + 1 < end) s_next = g_csr[e + 1];
                float4 v = *(const float4*)&feat[(size_t)s * DIM + lane * 4];
                a4.x += v.x; a4.y += v.y; a4.z += v.z; a4.w += v.w;
            }
            int d = end - beg;
            float sc = 1.0f / (float)(d > 0 ? d : 1);
            a4.x *= sc; a4.y *= sc; a4.z *= sc; a4.w *= sc;
        }
        float* dst = &agg_s[lrow * AGG_STRIDE + lane * 4];
        dst[0] = to_tf32(a4.x);
        dst[1] = to_tf32(a4.y);
        dst[2] = to_tf32(a4.z);
        dst[3] = to_tf32(a4.w);
    }

    // ---------------- Phase 2: GEMM ----------------
    int wr = wid & 3;           // warp rows: wr*32 .. +31
    int wc = wid >> 2;          // warp cols: wc*64 .. +63

    float acc[2][8][4];
#pragma unroll
    for (int nt = 0; nt < 8; ++nt) {
        int c = wc * 64 + nt * 8 + 2 * t;
        float b0 = b_l[c], b1 = b_l[c + 1];
#pragma unroll
        for (int mt = 0; mt < 2; ++mt) {
            acc[mt][nt][0] = b0; acc[mt][nt][1] = b1;
            acc[mt][nt][2] = b0; acc[mt][nt][3] = b1;
        }
    }

    int a_row = tid >> 3;            // +32 per i: rows 0..127
    int a_c4 = (tid & 7) * 4;
    int b_row = tid >> 5;            // +8 per i: rows 0..31
    int b_c4 = lane * 4;

    float4 ra[4], rb[4];

    auto load_B = [&](int kc) {
#pragma unroll
        for (int i = 0; i < 4; ++i)
            rb[i] = *(const float4*)&g_WT[(size_t)(kc * GKB + b_row + i * 8) * DIM + b_c4];
    };
    auto load_feat = [&](int kc) {   // kc in 4..7
        int ksrc = (kc - 4) * GKB;
#pragma unroll
        for (int i = 0; i < 4; ++i) {
            int grow = block_row + a_row + i * 32;
            ra[i] = make_float4(0.f, 0.f, 0.f, 0.f);
            if (grow < n)
                ra[i] = *(const float4*)&feat[(size_t)grow * DIM + ksrc + a_c4];
        }
    };

    load_B(0);
    __syncthreads();   // agg_s complete before MMA reads

#pragma unroll 1
    for (int kc = 0; kc < 8; ++kc) {
        int cb = (kc < 4) ? kc * GKB : (kc - 4) * GKB;   // A col base in agg_s

        if (kc >= 4) {   // store feat chunk over consumed agg columns
#pragma unroll
            for (int i = 0; i < 4; ++i) {
                float* dst = &agg_s[(a_row + i * 32) * AGG_STRIDE + cb + a_c4];
                dst[0] = to_tf32(ra[i].x); dst[1] = to_tf32(ra[i].y);
                dst[2] = to_tf32(ra[i].z); dst[3] = to_tf32(ra[i].w);
            }
        }
#pragma unroll
        for (int i = 0; i < 4; ++i)
            *(float4*)&Bs[(b_row + i * 8) * BS_STRIDE + b_c4] = rb[i];
        __syncthreads();

        if (kc < 7) load_B(kc + 1);
        if (kc >= 3 && kc < 7) load_feat(kc + 1);   // overlaps with MMA

#pragma unroll
        for (int ks = 0; ks < 4; ++ks) {
            int kb = ks * 8;
            uint32_t a[2][4];
#pragma unroll
            for (int mt = 0; mt < 2; ++mt) {
                int rbase = wr * 32 + mt * 16;
                const float* ap = &agg_s[(size_t)0];
                a[mt][0] = __float_as_uint(ap[(rbase + g) * AGG_STRIDE + cb + kb + t]);
                a[mt][1] = __float_as_uint(ap[(rbase + g + 8) * AGG_STRIDE + cb + kb + t]);
                a[mt][2] = __float_as_uint(ap[(rbase + g) * AGG_STRIDE + cb + kb + t + 4]);
                a[mt][3] = __float_as_uint(ap[(rbase + g + 8) * AGG_STRIDE + cb + kb + t + 4]);
            }
#pragma unroll
            for (int nt = 0; nt < 8; ++nt) {
                int cbn = wc * 64 + nt * 8 + g;
                uint32_t b0 = __float_as_uint(Bs[(kb + t) * BS_STRIDE + cbn]);
                uint32_t b1 = __float_as_uint(Bs[(kb + t + 4) * BS_STRIDE + cbn]);
#pragma unroll
                for (int mt = 0; mt < 2; ++mt) {
                    asm volatile(
                        "mma.sync.aligned.m16n8k8.row.col.f32.tf32.tf32.f32 "
                        "{%0,%1,%2,%3}, {%4,%5,%6,%7}, {%8,%9}, {%0,%1,%2,%3};"
                        : "+f"(acc[mt][nt][0]), "+f"(acc[mt][nt][1]),
                          "+f"(acc[mt][nt][2]), "+f"(acc[mt][nt][3])
                        : "r"(a[mt][0]), "r"(a[mt][1]), "r"(a[mt][2]), "r"(a[mt][3]),
                          "r"(b0), "r"(b1));
                }
            }
        }
        __syncthreads();
    }

    // epilogue
#pragma unroll
    for (int mt = 0; mt < 2; ++mt) {
        int r0 = block_row + wr * 32 + mt * 16 + g;
        int r1 = r0 + 8;
#pragma unroll
        for (int nt = 0; nt < 8; ++nt) {
            int c = wc * 64 + nt * 8 + 2 * t;
            if (r0 < n) {
                float2 v = make_float2(acc[mt][nt][0], acc[mt][nt][1]);
                *(float2*)&out[(size_t)r0 * DIM + c] = v;
            }
            if (r1 < n) {
                float2 v = make_float2(acc[mt][nt][2], acc[mt][nt][3]);
                *(float2*)&out[(size_t)r1 * DIM + c] = v;
            }
        }
    }
}

extern "C" void kernel_launch(void* const* d_in, const int* in_sizes, int n_in,
                              void* d_out, int out_size) {
    const float* feature = (const float*)d_in[0];
    const int*   ei      = (const int*)d_in[1];     // int32 (JAX x64 disabled)
    const float* W_l     = (const float*)d_in[2];
    const float* b_l     = (const float*)d_in[3];
    const float* W_r     = (const float*)d_in[4];
    float*       out     = (float*)d_out;

    int N = in_sizes[0] / DIM;
    int E = in_sizes[1] / 2;

    // allow 85 KB dynamic smem (idempotent attribute set; not a stream op)
    cudaFuncSetAttribute(fused_kernel,
                         cudaFuncAttributeMaxDynamicSharedMemorySize, SMEM_BYTES);

    init_kernel<<<(N + 255) / 256, 256>>>(W_l, W_r, N);          // 0
    hist_kernel<<<(E + 255) / 256, 256>>>(ei, E);                // 1

    int nblk = (N + SC_CHUNK - 1) / SC_CHUNK;                    // 49
    part_sum_kernel<<<nblk, SC_BLK>>>(N);                        // 2
    off_kernel<<<nblk, SC_BLK>>>(N, E, nblk);                    // 3
    scatter_kernel<<<(E + 255) / 256, 256>>>(ei, E);             // 4

    fused_kernel<<<(N + GBM - 1) / GBM, 256, SMEM_BYTES>>>(feature, b_l, out, N);  // 5 (ncu slot)
}

// round 7
// speedup vs baseline: 1.0904x; 1.0904x over previous
#include <cuda_runtime.h>
#include <cuda_bf16.h>
#include <stdint.h>

// Problem constants: N=100000 nodes, E=600000 edges, D=128.
#define N_MAX 100000
#define E_MAX 600000
#define DIM   128

// scan geometry
#define SC_BLK   256
#define SC_PER   8
#define SC_CHUNK (SC_BLK * SC_PER)            // 2048

// ---- device scratch (no cudaMalloc allowed) ----
__device__ int   g_deg[N_MAX];
__device__ int   g_off[N_MAX + 1];
__device__ int   g_cur[N_MAX];
__device__ int   g_csr[E_MAX];
__device__ __align__(16) float g_agg[(size_t)N_MAX * DIM];  // tf32-rounded means
__device__ __align__(16) float g_WT[256 * DIM];             // [Wl ; Wr]^T tf32

__device__ __forceinline__ float to_tf32(float x) {
    float y;
    asm("cvt.rna.tf32.f32 %0, %1;" : "=f"(y) : "f"(x));
    return y;
}

// ---------------------------------------------------------------------------
// 0) merged init: zero degree counters + transpose/round weights
__global__ void init_kernel(const float* __restrict__ Wl,
                            const float* __restrict__ Wr, int n) {
    int i = blockIdx.x * blockDim.x + threadIdx.x;
    if (i < n) g_deg[i] = 0;
    if (i < 256 * DIM) {
        int k = i >> 7;
        int j = i & 127;
        float v = (k < DIM) ? Wl[j * DIM + k] : Wr[j * DIM + (k - DIM)];
        g_WT[i] = to_tf32(v);
    }
}

// 1) histogram of destination nodes (edge_index is int32)
__global__ void hist_kernel(const int* __restrict__ ei, int E) {
    int i = blockIdx.x * blockDim.x + threadIdx.x;
    if (i < E) {
        int dst = ei[E + i];
        if (dst >= 0 && dst < N_MAX) atomicAdd(&g_deg[dst], 1);
    }
}

// 2) offsets in ONE kernel: each block reduces g_deg[0..chunk_start) for its
//    exclusive chunk prefix (<=400KB coalesced L2 reads), then scans its chunk.
__global__ void off_kernel(int n, int E) {
    __shared__ int s[SC_BLK];
    __shared__ int s_prefix;
    int t = threadIdx.x;
    int chunk_start = blockIdx.x * SC_CHUNK;

    // block-wide reduce of the full prefix
    int pre = 0;
    for (int i = t; i < chunk_start; i += SC_BLK) pre += g_deg[i];
    s[t] = pre;
    __syncthreads();
#pragma unroll
    for (int off = SC_BLK / 2; off > 0; off >>= 1) {
        if (t < off) s[t] += s[t + off];
        __syncthreads();
    }
    if (t == 0) s_prefix = s[0];
    __syncthreads();
    int chunk_prefix = s_prefix;
    __syncthreads();   // s[] reused below

    // scan own chunk
    int base = chunk_start + t * SC_PER;
    int v[SC_PER];
    int sum = 0;
#pragma unroll
    for (int j = 0; j < SC_PER; ++j) {
        int i = base + j;
        v[j] = (i < n) ? g_deg[i] : 0;
        sum += v[j];
    }
    s[t] = sum;
    __syncthreads();
#pragma unroll
    for (int off = 1; off < SC_BLK; off <<= 1) {
        int tmp = (t >= off) ? s[t - off] : 0;
        __syncthreads();
        s[t] += tmp;
        __syncthreads();
    }
    int run = chunk_prefix + s[t] - sum;   // exclusive prefix for this thread
#pragma unroll
    for (int j = 0; j < SC_PER; ++j) {
        int i = base + j;
        if (i < n) {
            g_off[i] = run;
            g_cur[i] = run;
            run += v[j];
        }
    }
    if (blockIdx.x == 0 && t == 0) g_off[n] = E;
}

// 3) scatter src ids into CSR slots
__global__ void scatter_kernel(const int* __restrict__ ei, int E) {
    int i = blockIdx.x * blockDim.x + threadIdx.x;
    if (i < E) {
        int src = ei[i];
        int dst = ei[E + i];
        if (dst >= 0 && dst < N_MAX) {
            int pos = atomicAdd(&g_cur[dst], 1);
            if (pos >= 0 && pos < E_MAX) g_csr[pos] = src;
        }
    }
}

// 4) mean aggregation: one warp per node, 2-edge unroll for MLP
__global__ void agg_kernel(const float* __restrict__ feat, int n) {
    int gwarp = (blockIdx.x * blockDim.x + threadIdx.x) >> 5;
    int lane = threadIdx.x & 31;
    if (gwarp >= n) return;

    int beg = g_off[gwarp];
    int end = g_off[gwarp + 1];
    float4 acc0 = make_float4(0.f, 0.f, 0.f, 0.f);
    float4 acc1 = make_float4(0.f, 0.f, 0.f, 0.f);

    int e = beg;
    for (; e + 1 < end; e += 2) {
        int s0 = g_csr[e];
        int s1 = g_csr[e + 1];
        float4 v0 = *(const float4*)&feat[(size_t)s0 * DIM + lane * 4];
        float4 v1 = *(const float4*)&feat[(size_t)s1 * DIM + lane * 4];
        acc0.x += v0.x; acc0.y += v0.y; acc0.z += v0.z; acc0.w += v0.w;
        acc1.x += v1.x; acc1.y += v1.y; acc1.z += v1.z; acc1.w += v1.w;
    }
    if (e < end) {
        int s0 = g_csr[e];
        float4 v0 = *(const float4*)&feat[(size_t)s0 * DIM + lane * 4];
        acc0.x += v0.x; acc0.y += v0.y; acc0.z += v0.z; acc0.w += v0.w;
    }
    acc0.x += acc1.x; acc0.y += acc1.y; acc0.z += acc1.z; acc0.w += acc1.w;

    int d = end - beg;
    float scale = 1.0f / (float)(d > 0 ? d : 1);
    float4 o;
    o.x = to_tf32(acc0.x * scale);
    o.y = to_tf32(acc0.y * scale);
    o.z = to_tf32(acc0.z * scale);
    o.w = to_tf32(acc0.w * scale);
    *(float4*)&g_agg[(size_t)gwarp * DIM + lane * 4] = o;
}

// ---------------------------------------------------------------------------
// tf32 tensor-core GEMM, software-pipelined (register prefetch of next chunk):
// out[N,128] = [agg | feat](N,256) x g_WT(256,128) + b_l
#define GBM 128
#define GKB 32
#define AS_STRIDE 36   // banks (4g+t): conflict-free A frag loads
#define BS_STRIDE 136  // banks (8t+g): conflict-free B frag loads

__global__ __launch_bounds__(256, 2)
void gemm_tc_kernel(const float* __restrict__ feat,
                    const float* __restrict__ b_l,
                    float* __restrict__ out, int n) {
    __shared__ float As[GBM * AS_STRIDE];   // 128 x 32 (padded)
    __shared__ float Bs[GKB * BS_STRIDE];   // 32 x 128 (padded)

    int tid = threadIdx.x;
    int wid = tid >> 5;
    int lane = tid & 31;
    int g = lane >> 2, t = lane & 3;

    int wr = wid & 3;           // warp rows: wr*32 .. +31
    int wc = wid >> 2;          // warp cols: wc*64 .. +63
    int block_row = blockIdx.x * GBM;

    float acc[2][8][4];
#pragma unroll
    for (int nt = 0; nt < 8; ++nt) {
        int c = wc * 64 + nt * 8 + 2 * t;
        float b0 = b_l[c], b1 = b_l[c + 1];
#pragma unroll
        for (int mt = 0; mt < 2; ++mt) {
            acc[mt][nt][0] = b0; acc[mt][nt][1] = b1;
            acc[mt][nt][2] = b0; acc[mt][nt][3] = b1;
        }
    }

    int a_row = tid >> 3;            // +32 per i: rows 0..127
    int a_c4 = (tid & 7) * 4;
    int b_row = tid >> 5;            // +8 per i: rows 0..31
    int b_c4 = lane * 4;

    float4 ra[4], rb[4];

    auto load_chunk = [&](int kc) {
        const float* Asrc = (kc < 4) ? g_agg : feat;
        int ksrc = (kc * GKB) & 127;
#pragma unroll
        for (int i = 0; i < 4; ++i) {
            int grow = block_row + a_row + i * 32;
            ra[i] = make_float4(0.f, 0.f, 0.f, 0.f);
            if (grow < n)
                ra[i] = *(const float4*)&Asrc[(size_t)grow * DIM + ksrc + a_c4];
        }
#pragma unroll
        for (int i = 0; i < 4; ++i)
            rb[i] = *(const float4*)&g_WT[(size_t)(kc * GKB + b_row + i * 8) * DIM + b_c4];
    };

    load_chunk(0);

#pragma unroll 1
    for (int kc = 0; kc < 8; ++kc) {
        bool need_cvt = (kc >= 4);   // feat chunks: round to tf32 at STS
#pragma unroll
        for (int i = 0; i < 4; ++i) {
            float* dst = &As[(a_row + i * 32) * AS_STRIDE + a_c4];
            if (need_cvt) {
                dst[0] = to_tf32(ra[i].x); dst[1] = to_tf32(ra[i].y);
                dst[2] = to_tf32(ra[i].z); dst[3] = to_tf32(ra[i].w);
            } else {
                dst[0] = ra[i].x; dst[1] = ra[i].y;
                dst[2] = ra[i].z; dst[3] = ra[i].w;
            }
        }
#pragma unroll
        for (int i = 0; i < 4; ++i)
            *(float4*)&Bs[(b_row + i * 8) * BS_STRIDE + b_c4] = rb[i];
        __syncthreads();

        if (kc < 7) load_chunk(kc + 1);   // overlaps with MMA below

#pragma unroll
        for (int ks = 0; ks < 4; ++ks) {
            int kb = ks * 8;
            uint32_t a[2][4];
#pragma unroll
            for (int mt = 0; mt < 2; ++mt) {
                int rb_ = wr * 32 + mt * 16;
                a[mt][0] = __float_as_uint(As[(rb_ + g) * AS_STRIDE + kb + t]);
                a[mt][1] = __float_as_uint(As[(rb_ + g + 8) * AS_STRIDE + kb + t]);
                a[mt][2] = __float_as_uint(As[(rb_ + g) * AS_STRIDE + kb + t + 4]);
                a[mt][3] = __float_as_uint(As[(rb_ + g + 8) * AS_STRIDE + kb + t + 4]);
            }
#pragma unroll
            for (int nt = 0; nt < 8; ++nt) {
                int cb = wc * 64 + nt * 8 + g;
                uint32_t b0 = __float_as_uint(Bs[(kb + t) * BS_STRIDE + cb]);
                uint32_t b1 = __float_as_uint(Bs[(kb + t + 4) * BS_STRIDE + cb]);
#pragma unroll
                for (int mt = 0; mt < 2; ++mt) {
                    asm volatile(
                        "mma.sync.aligned.m16n8k8.row.col.f32.tf32.tf32.f32 "
                        "{%0,%1,%2,%3}, {%4,%5,%6,%7}, {%8,%9}, {%0,%1,%2,%3};"
                        : "+f"(acc[mt][nt][0]), "+f"(acc[mt][nt][1]),
                          "+f"(acc[mt][nt][2]), "+f"(acc[mt][nt][3])
                        : "r"(a[mt][0]), "r"(a[mt][1]), "r"(a[mt][2]), "r"(a[mt][3]),
                          "r"(b0), "r"(b1));
                }
            }
        }
        __syncthreads();
    }

    // epilogue
#pragma unroll
    for (int mt = 0; mt < 2; ++mt) {
        int r0 = block_row + wr * 32 + mt * 16 + g;
        int r1 = r0 + 8;
#pragma unroll
        for (int nt = 0; nt < 8; ++nt) {
            int c = wc * 64 + nt * 8 + 2 * t;
            if (r0 < n) {
                float2 v = make_float2(acc[mt][nt][0], acc[mt][nt][1]);
                *(float2*)&out[(size_t)r0 * DIM + c] = v;
            }
            if (r1 < n) {
                float2 v = make_float2(acc[mt][nt][2], acc[mt][nt][3]);
                *(float2*)&out[(size_t)r1 * DIM + c] = v;
            }
        }
    }
}

extern "C" void kernel_launch(void* const* d_in, const int* in_sizes, int n_in,
                              void* d_out, int out_size) {
    const float* feature = (const float*)d_in[0];
    const int*   ei      = (const int*)d_in[1];     // int32 (JAX x64 disabled)
    const float* W_l     = (const float*)d_in[2];
    const float* b_l     = (const float*)d_in[3];
    const float* W_r     = (const float*)d_in[4];
    float*       out     = (float*)d_out;

    int N = in_sizes[0] / DIM;
    int E = in_sizes[1] / 2;

    init_kernel<<<(N + 255) / 256, 256>>>(W_l, W_r, N);          // 0
    hist_kernel<<<(E + 255) / 256, 256>>>(ei, E);                // 1

    int nblk = (N + SC_CHUNK - 1) / SC_CHUNK;                    // 49
    off_kernel<<<nblk, SC_BLK>>>(N, E);                          // 2
    scatter_kernel<<<(E + 255) / 256, 256>>>(ei, E);             // 3

    int agg_blocks = (N + 7) / 8;
    agg_kernel<<<agg_blocks, 256>>>(feature, N);                 // 4

    gemm_tc_kernel<<<(N + GBM - 1) / GBM, 256>>>(feature, b_l, out, N);  // 5 (ncu slot)
}

// round 8
// speedup vs baseline: 1.1591x; 1.0630x over previous
#include <cuda_runtime.h>
#include <cuda_bf16.h>
#include <stdint.h>

// Problem constants: N=100000 nodes, E=600000 edges, D=128.
#define N_MAX 100000
#define E_MAX 600000
#define DIM   128

// multi-block scan geometry
#define SC_BLK   256
#define SC_PER   8
#define SC_CHUNK (SC_BLK * SC_PER)            // 2048
#define SC_NBLK  ((N_MAX + SC_CHUNK - 1) / SC_CHUNK)   // 49 (must be <= 64)

// edge-kernel batching
#define EB 4

// ---- device scratch (no cudaMalloc allowed) ----
__device__ int   g_deg[N_MAX];
__device__ int   g_off[N_MAX + 1];
__device__ int   g_cur[N_MAX];
__device__ int   g_csr[E_MAX];
__device__ int   g_part[64];
__device__ __align__(16) float g_agg[(size_t)N_MAX * DIM];  // tf32-rounded means
__device__ __align__(16) float g_WT[256 * DIM];             // [Wl ; Wr]^T tf32

__device__ __forceinline__ float to_tf32(float x) {
    float y;
    asm("cvt.rna.tf32.f32 %0, %1;" : "=f"(y) : "f"(x));
    return y;
}

// ---------------------------------------------------------------------------
// 0) merged init: zero degree counters + transpose/round weights
__global__ void init_kernel(const float* __restrict__ Wl,
                            const float* __restrict__ Wr, int n) {
    int i = blockIdx.x * blockDim.x + threadIdx.x;
    if (i < n) g_deg[i] = 0;
    if (i < 256 * DIM) {
        int k = i >> 7;
        int j = i & 127;
        float v = (k < DIM) ? Wl[j * DIM + k] : Wr[j * DIM + (k - DIM)];
        g_WT[i] = to_tf32(v);
    }
}

// 1) histogram of destination nodes — 4 edges/thread, batched loads (MLP=4)
__global__ void hist_kernel(const int* __restrict__ ei, int E) {
    int base = blockIdx.x * (256 * EB) + threadIdx.x;
    int d[EB];
#pragma unroll
    for (int k = 0; k < EB; ++k) {
        int i = base + k * 256;
        d[k] = (i < E) ? ei[E + i] : -1;
    }
#pragma unroll
    for (int k = 0; k < EB; ++k)
        if (d[k] >= 0 && d[k] < N_MAX) atomicAdd(&g_deg[d[k]], 1);
}

// 2) per-chunk partial sums
__global__ void part_sum_kernel(int n) {
    __shared__ int s[SC_BLK];
    int t = threadIdx.x;
    int base = blockIdx.x * SC_CHUNK + t * SC_PER;
    int sum = 0;
#pragma unroll
    for (int j = 0; j < SC_PER; ++j) {
        int i = base + j;
        if (i < n) sum += g_deg[i];
    }
    s[t] = sum;
    __syncthreads();
#pragma unroll
    for (int off = SC_BLK / 2; off > 0; off >>= 1) {
        if (t < off) s[t] += s[t + off];
        __syncthreads();
    }
    if (t == 0) g_part[blockIdx.x] = s[0];
}

// 3) offsets: each block scans the (<=64) chunk partials itself, then re-scans
//    its own 2048-element chunk and writes g_off / g_cur.
__global__ void off_kernel(int n, int E, int nblk) {
    __shared__ int sp[64];
    __shared__ int s[SC_BLK];
    int t = threadIdx.x;

    if (t < 64) sp[t] = (t < nblk) ? g_part[t] : 0;
    __syncthreads();
#pragma unroll
    for (int off = 1; off < 64; off <<= 1) {
        int tmp = (t < 64 && t >= off) ? sp[t - off] : 0;
        __syncthreads();
        if (t < 64) sp[t] += tmp;
        __syncthreads();
    }
    // sp[] = INCLUSIVE prefix of chunk partials.

    int base = blockIdx.x * SC_CHUNK + t * SC_PER;
    int v[SC_PER];
    int sum = 0;
#pragma unroll
    for (int j = 0; j < SC_PER; ++j) {
        int i = base + j;
        v[j] = (i < n) ? g_deg[i] : 0;
        sum += v[j];
    }
    s[t] = sum;
    __syncthreads();
#pragma unroll
    for (int off = 1; off < SC_BLK; off <<= 1) {
        int tmp = (t >= off) ? s[t - off] : 0;
        __syncthreads();
        s[t] += tmp;
        __syncthreads();
    }
    int block_total = s[SC_BLK - 1];
    int chunk_prefix = sp[blockIdx.x] - block_total;
    int run = chunk_prefix + s[t] - sum;
#pragma unroll
    for (int j = 0; j < SC_PER; ++j) {
        int i = base + j;
        if (i < n) {
            g_off[i] = run;
            g_cur[i] = run;
            run += v[j];
        }
    }
    if (blockIdx.x == 0 && t == 0) g_off[n] = E;
}

// 4) scatter src ids into CSR slots — 4 edges/thread, batched loads (MLP=8)
__global__ void scatter_kernel(const int* __restrict__ ei, int E) {
    int base = blockIdx.x * (256 * EB) + threadIdx.x;
    int src[EB], dst[EB];
#pragma unroll
    for (int k = 0; k < EB; ++k) {
        int i = base + k * 256;
        src[k] = (i < E) ? ei[i] : 0;
        dst[k] = (i < E) ? ei[E + i] : -1;
    }
#pragma unroll
    for (int k = 0; k < EB; ++k) {
        if (dst[k] >= 0 && dst[k] < N_MAX) {
            int pos = atomicAdd(&g_cur[dst[k]], 1);
            g_csr[pos] = src[k];   // pos < E guaranteed by offsets+degrees
        }
    }
}

// 5) mean aggregation: one warp per node; result stored tf32-rounded
__global__ void agg_kernel(const float* __restrict__ feat, int n) {
    int gwarp = (blockIdx.x * blockDim.x + threadIdx.x) >> 5;
    int lane = threadIdx.x & 31;
    if (gwarp >= n) return;

    int beg = g_off[gwarp];
    int end = g_off[gwarp + 1];
    float4 acc = make_float4(0.f, 0.f, 0.f, 0.f);

    int s_next = (beg < end) ? g_csr[beg] : 0;
    for (int e = beg; e < end; ++e) {
        int s = s_next;
        if (e + 1 < end) s_next = g_csr[e + 1];   // prefetch next index
        float4 v = *(const float4*)&feat[(size_t)s * DIM + lane * 4];
        acc.x += v.x; acc.y += v.y; acc.z += v.z; acc.w += v.w;
    }
    int d = end - beg;
    float scale = 1.0f / (float)(d > 0 ? d : 1);
    float4 o;
    o.x = to_tf32(acc.x * scale);
    o.y = to_tf32(acc.y * scale);
    o.z = to_tf32(acc.z * scale);
    o.w = to_tf32(acc.w * scale);
    *(float4*)&g_agg[(size_t)gwarp * DIM + lane * 4] = o;
}

// ---------------------------------------------------------------------------
// tf32 tensor-core GEMM, software-pipelined (register prefetch of next chunk):
// out[N,128] = [agg | feat](N,256) x g_WT(256,128) + b_l
#define GBM 128
#define GKB 32
#define AS_STRIDE 36   // banks (4g+t): conflict-free A frag loads
#define BS_STRIDE 136  // banks (8t+g): conflict-free B frag loads

__global__ __launch_bounds__(256, 2)
void gemm_tc_kernel(const float* __restrict__ feat,
                    const float* __restrict__ b_l,
                    float* __restrict__ out, int n) {
    __shared__ float As[GBM * AS_STRIDE];   // 128 x 32 (padded)
    __shared__ float Bs[GKB * BS_STRIDE];   // 32 x 128 (padded)

    int tid = threadIdx.x;
    int wid = tid >> 5;
    int lane = tid & 31;
    int g = lane >> 2, t = lane & 3;

    int wr = wid & 3;           // warp rows: wr*32 .. +31
    int wc = wid >> 2;          // warp cols: wc*64 .. +63
    int block_row = blockIdx.x * GBM;

    float acc[2][8][4];
#pragma unroll
    for (int nt = 0; nt < 8; ++nt) {
        int c = wc * 64 + nt * 8 + 2 * t;
        float b0 = b_l[c], b1 = b_l[c + 1];
#pragma unroll
        for (int mt = 0; mt < 2; ++mt) {
            acc[mt][nt][0] = b0; acc[mt][nt][1] = b1;
            acc[mt][nt][2] = b0; acc[mt][nt][3] = b1;
        }
    }

    int a_row = tid >> 3;            // +32 per i: rows 0..127
    int a_c4 = (tid & 7) * 4;
    int b_row = tid >> 5;            // +8 per i: rows 0..31
    int b_c4 = lane * 4;

    float4 ra[4], rb[4];

    auto load_chunk = [&](int kc) {
        const float* Asrc = (kc < 4) ? g_agg : feat;
        int ksrc = (kc * GKB) & 127;
#pragma unroll
        for (int i = 0; i < 4; ++i) {
            int grow = block_row + a_row + i * 32;
            ra[i] = make_float4(0.f, 0.f, 0.f, 0.f);
            if (grow < n)
                ra[i] = *(const float4*)&Asrc[(size_t)grow * DIM + ksrc + a_c4];
        }
#pragma unroll
        for (int i = 0; i < 4; ++i)
            rb[i] = *(const float4*)&g_WT[(size_t)(kc * GKB + b_row + i * 8) * DIM + b_c4];
    };

    load_chunk(0);

#pragma unroll 1
    for (int kc = 0; kc < 8; ++kc) {
        bool need_cvt = (kc >= 4);   // feat chunks: round to tf32 at STS
#pragma unroll
        for (int i = 0; i < 4; ++i) {
            float* dst = &As[(a_row + i * 32) * AS_STRIDE + a_c4];
            if (need_cvt) {
                dst[0] = to_tf32(ra[i].x); dst[1] = to_tf32(ra[i].y);
                dst[2] = to_tf32(ra[i].z); dst[3] = to_tf32(ra[i].w);
            } else {
                dst[0] = ra[i].x; dst[1] = ra[i].y;
                dst[2] = ra[i].z; dst[3] = ra[i].w;
            }
        }
#pragma unroll
        for (int i = 0; i < 4; ++i)
            *(float4*)&Bs[(b_row + i * 8) * BS_STRIDE + b_c4] = rb[i];
        __syncthreads();

        if (kc < 7) load_chunk(kc + 1);   // overlaps with MMA below

#pragma unroll
        for (int ks = 0; ks < 4; ++ks) {
            int kb = ks * 8;
            uint32_t a[2][4];
#pragma unroll
            for (int mt = 0; mt < 2; ++mt) {
                int rb_ = wr * 32 + mt * 16;
                a[mt][0] = __float_as_uint(As[(rb_ + g) * AS_STRIDE + kb + t]);
                a[mt][1] = __float_as_uint(As[(rb_ + g + 8) * AS_STRIDE + kb + t]);
                a[mt][2] = __float_as_uint(As[(rb_ + g) * AS_STRIDE + kb + t + 4]);
                a[mt][3] = __float_as_uint(As[(rb_ + g + 8) * AS_STRIDE + kb + t + 4]);
            }
#pragma unroll
            for (int nt = 0; nt < 8; ++nt) {
                int cb = wc * 64 + nt * 8 + g;
                uint32_t b0 = __float_as_uint(Bs[(kb + t) * BS_STRIDE + cb]);
                uint32_t b1 = __float_as_uint(Bs[(kb + t + 4) * BS_STRIDE + cb]);
#pragma unroll
                for (int mt = 0; mt < 2; ++mt) {
                    asm volatile(
                        "mma.sync.aligned.m16n8k8.row.col.f32.tf32.tf32.f32 "
                        "{%0,%1,%2,%3}, {%4,%5,%6,%7}, {%8,%9}, {%0,%1,%2,%3};"
                        : "+f"(acc[mt][nt][0]), "+f"(acc[mt][nt][1]),
                          "+f"(acc[mt][nt][2]), "+f"(acc[mt][nt][3])
                        : "r"(a[mt][0]), "r"(a[mt][1]), "r"(a[mt][2]), "r"(a[mt][3]),
                          "r"(b0), "r"(b1));
                }
            }
        }
        __syncthreads();
    }

    // epilogue
#pragma unroll
    for (int mt = 0; mt < 2; ++mt) {
        int r0 = block_row + wr * 32 + mt * 16 + g;
        int r1 = r0 + 8;
#pragma unroll
        for (int nt = 0; nt < 8; ++nt) {
            int c = wc * 64 + nt * 8 + 2 * t;
            if (r0 < n) {
                float2 v = make_float2(acc[mt][nt][0], acc[mt][nt][1]);
                *(float2*)&out[(size_t)r0 * DIM + c] = v;
            }
            if (r1 < n) {
                float2 v = make_float2(acc[mt][nt][2], acc[mt][nt][3]);
                *(float2*)&out[(size_t)r1 * DIM + c] = v;
            }
        }
    }
}

extern "C" void kernel_launch(void* const* d_in, const int* in_sizes, int n_in,
                              void* d_out, int out_size) {
    const float* feature = (const float*)d_in[0];
    const int*   ei      = (const int*)d_in[1];     // int32 (JAX x64 disabled)
    const float* W_l     = (const float*)d_in[2];
    const float* b_l     = (const float*)d_in[3];
    const float* W_r     = (const float*)d_in[4];
    float*       out     = (float*)d_out;

    int N = in_sizes[0] / DIM;
    int E = in_sizes[1] / 2;

    init_kernel<<<(N + 255) / 256, 256>>>(W_l, W_r, N);          // 0
    hist_kernel<<<(E + 256 * EB - 1) / (256 * EB), 256>>>(ei, E);// 1

    int nblk = (N + SC_CHUNK - 1) / SC_CHUNK;                    // 49
    part_sum_kernel<<<nblk, SC_BLK>>>(N);                        // 2
    off_kernel<<<nblk, SC_BLK>>>(N, E, nblk);                    // 3
    scatter_kernel<<<(E + 256 * EB - 1) / (256 * EB), 256>>>(ei, E); // 4

    int agg_blocks = (N + 7) / 8;
    agg_kernel<<<agg_blocks, 256>>>(feature, N);                 // 5 (ncu slot)

    gemm_tc_kernel<<<(N + GBM - 1) / GBM, 256>>>(feature, b_l, out, N);  // 6
}